// round 14
// baseline (speedup 1.0000x reference)
#include <cuda_runtime.h>
#include <cuda_bf16.h>
#include <math.h>

// SurfNetwork v12: v6 MLP verbatim + two-deep NON-BLOCKING prefetch.
// Carries xv (row+2gs x-indices) and raw f4[6] (row+1 gathers) across
// iterations; gathers issue at iteration top and are consumed one full
// iteration later (no pkbf fold at issue site -> no scoreboard stall).
// 3 blocks/SM persistent.

#define BN   128
#define LVL  6
#define DIRD 16
#define GEO  18

#define SW0G 20
#define SW1  36
#define SW2  36
#define SAG  20
#define SCB  9

typedef unsigned int u32;

#define O_W0GT 0
#define O_W1T  1280
#define O_W2T  3584
#define O_W0D  3872
#define O_B0   4896
#define O_B1   4960
#define O_B2   5024
#define O_BASE 5032
#define O_SIG  5096
#define O_MAX  5224
#define O_COL  5228
#define O_ACTG 5240
#define O_COLB 7800
#define SMEM_WORDS 8952
#define SMEM_BYTES (SMEM_WORDS * 4)   // 35808

__device__ __forceinline__ u32 pkbf(float lo, float hi) {
    u32 r; asm("cvt.rn.bf16x2.f32 %0, %1, %2;" : "=r"(r) : "f"(hi), "f"(lo));
    return r;
}
__device__ __forceinline__ u32 pkrelu(float lo, float hi) {
    return pkbf(fmaxf(lo, 0.0f), fmaxf(hi, 0.0f));
}
__device__ __forceinline__ void mma16(float* c, const u32* a, u32 b0, u32 b1) {
    asm volatile(
        "mma.sync.aligned.m16n8k16.row.col.f32.bf16.bf16.f32 "
        "{%0,%1,%2,%3},{%4,%5,%6,%7},{%8,%9},{%0,%1,%2,%3};"
        : "+f"(c[0]), "+f"(c[1]), "+f"(c[2]), "+f"(c[3])
        : "r"(a[0]), "r"(a[1]), "r"(a[2]), "r"(a[3]), "r"(b0), "r"(b1));
}
__device__ __forceinline__ int agix(int row, int j) {
    return row * SAG + (j ^ ((row >> 3) & 3));
}

__global__ void __launch_bounds__(128, 3)
surf_v12(const int* __restrict__ x,
         const float* __restrict__ dvec,
         const float4* __restrict__ gw,
         const float* __restrict__ W0, const float* __restrict__ b0,
         const float* __restrict__ W1, const float* __restrict__ b1,
         const float* __restrict__ W2, const float* __restrict__ b2,
         float* __restrict__ outSigma, float* __restrict__ outColor,
         int B)
{
    extern __shared__ float sm[];
    u32* smu = (u32*)sm;
    const int tid  = threadIdx.x;
    const int lane = tid & 31;
    const int warp = tid >> 5;
    const int grp  = lane >> 2;
    const int tig  = lane & 3;

    // ---------- stage weights (transposed, bf16x2) ----------
    for (int i = tid; i < 64 * SW0G; i += 128) {
        int n = i / SW0G, kk = i - n * SW0G;
        u32 v = 0;
        if (kk < 16) {
            int g0 = 2 * kk, g1 = 2 * kk + 1;
            float lo = (g0 < GEO) ? W0[(DIRD + g0) * 64 + n] : 0.0f;
            float hi = (g1 < GEO) ? W0[(DIRD + g1) * 64 + n] : 0.0f;
            v = pkbf(lo, hi);
        }
        smu[O_W0GT + i] = v;
    }
    for (int i = tid; i < 64 * SW1; i += 128) {
        int n = i / SW1, kk = i - n * SW1;
        u32 v = 0;
        if (kk < 32) v = pkbf(W1[(2 * kk) * 64 + n], W1[(2 * kk + 1) * 64 + n]);
        smu[O_W1T + i] = v;
    }
    for (int i = tid; i < 8 * SW2; i += 128) {
        int n = i / SW2, kk = i - n * SW2;
        u32 v = 0;
        if (kk < 32 && n < 3) v = pkbf(W2[(2 * kk) * 3 + n], W2[(2 * kk + 1) * 3 + n]);
        smu[O_W2T + i] = v;
    }
    for (int i = tid; i < DIRD * 64; i += 128) sm[O_W0D + i] = W0[i];
    if (tid < 64) { sm[O_B0 + tid] = b0[tid]; sm[O_B1 + tid] = b1[tid]; }
    if (tid < 8)  sm[O_B2 + tid] = (tid < 3) ? b2[tid] : 0.0f;
    for (int j = 9; j < 16; j++) smu[O_ACTG + agix(tid, j)] = 0;
    __syncthreads();

    const int gstride = gridDim.x;
    int row = blockIdx.x;

    // ---------- prologue: f4/d for row, xv for row+gs ----------
    float4 f4[6];
    float  dpre[DIRD];
    int2   xv0, xv1, xv2;
    xv0 = make_int2(0, 0); xv1 = xv0; xv2 = xv0;
    {
        const int2* xp2 = (const int2*)(x + ((size_t)row * BN + tid) * LVL);
        int2 a0 = __ldg(xp2), a1 = __ldg(xp2 + 1), a2 = __ldg(xp2 + 2);
        if (tid < 64) {
            const float* dd = dvec + (size_t)row * DIRD;
            #pragma unroll
            for (int i = 0; i < DIRD; i++) dpre[i] = __ldg(dd + i);
        }
        f4[0] = __ldg(gw + a0.x); f4[1] = __ldg(gw + a0.y);
        f4[2] = __ldg(gw + a1.x); f4[3] = __ldg(gw + a1.y);
        f4[4] = __ldg(gw + a2.x); f4[5] = __ldg(gw + a2.y);
        if (row + gstride < B) {
            const int2* xn = (const int2*)(x + ((size_t)(row + gstride) * BN + tid) * LVL);
            xv0 = __ldg(xn); xv1 = __ldg(xn + 1); xv2 = __ldg(xn + 2);
        }
    }

    while (row < B) {
        const int nrow = row + gstride;
        const bool pn = nrow < B;

        // ============ phase 1: consume prefetched data ============
        if (tid < 64) {
            float acc = sm[O_B0 + tid];
            #pragma unroll
            for (int i = 0; i < DIRD; i++)
                acc = fmaf(dpre[i], sm[O_W0D + i * 64 + tid], acc);
            sm[O_BASE + tid] = acc;
        }
        float sg = 1.0f;
        float geo[GEO];
        #pragma unroll
        for (int l = 0; l < LVL; l++) {
            float4 f = f4[l];
            sg *= fminf(fmaxf(f.x, 0.0f), 1.0f);
            geo[3 * l] = f.y; geo[3 * l + 1] = f.z; geo[3 * l + 2] = f.w;
        }
        sg += 1e-4f;
        sm[O_SIG + tid] = sg;
        #pragma unroll
        for (int j = 0; j < 9; j++)
            smu[O_ACTG + agix(tid, j)] = pkbf(geo[2 * j], geo[2 * j + 1]);

        // ---- issue next-row memory NOW (raw, consumed next iteration) ----
        if (pn) {
            f4[0] = __ldg(gw + xv0.x); f4[1] = __ldg(gw + xv0.y);
            f4[2] = __ldg(gw + xv1.x); f4[3] = __ldg(gw + xv1.y);
            f4[4] = __ldg(gw + xv2.x); f4[5] = __ldg(gw + xv2.y);
            if (nrow + gstride < B) {
                const int2* xn = (const int2*)(x + ((size_t)(nrow + gstride) * BN + tid) * LVL);
                xv0 = __ldg(xn); xv1 = __ldg(xn + 1); xv2 = __ldg(xn + 2);
            }
            if (tid < 64) {
                const float* dd = dvec + (size_t)nrow * DIRD;
                #pragma unroll
                for (int i = 0; i < DIRD; i++) dpre[i] = __ldg(dd + i);
            }
        }

        float m = sg;
        #pragma unroll
        for (int o = 16; o; o >>= 1) m = fmaxf(m, __shfl_xor_sync(0xffffffffu, m, o));
        if (lane == 0) sm[O_MAX + warp] = m;
        __syncthreads();   // (A)
        m = fmaxf(fmaxf(sm[O_MAX + 0], sm[O_MAX + 1]), fmaxf(sm[O_MAX + 2], sm[O_MAX + 3]));

        float sigma = sg / m;
        outSigma[(size_t)row * BN + tid] = sigma;
        float tb = tid ? 1.0f - sm[O_SIG + tid - 1] / m : 1.0f;
        float cw = tb * sigma;

        const int r0 = warp * 32 + grp;

        // ============ layer 0 -> A1 registers ============
        u32 A1[2][4][4];
        {
            u32 Ag[2][2][4];
            const u32* AG = smu + O_ACTG;
            #pragma unroll
            for (int mt = 0; mt < 2; mt++) {
                int rA = r0 + mt * 16, rB = rA + 8;
                #pragma unroll
                for (int k = 0; k < 2; k++) {
                    Ag[mt][k][0] = AG[agix(rA, k * 8 + tig)];
                    Ag[mt][k][1] = AG[agix(rB, k * 8 + tig)];
                    Ag[mt][k][2] = AG[agix(rA, k * 8 + 4 + tig)];
                    Ag[mt][k][3] = AG[agix(rB, k * 8 + 4 + tig)];
                }
            }
            const u32* WT = smu + O_W0GT;
            #pragma unroll
            for (int kg = 0; kg < 4; kg++) {
                float Ca[2][4], Cb[2][4];
                #pragma unroll
                for (int mt = 0; mt < 2; mt++) {
                    float v0 = sm[O_BASE + (2 * kg) * 8 + 2 * tig];
                    float v1 = sm[O_BASE + (2 * kg) * 8 + 2 * tig + 1];
                    Ca[mt][0] = v0; Ca[mt][1] = v1; Ca[mt][2] = v0; Ca[mt][3] = v1;
                    v0 = sm[O_BASE + (2 * kg + 1) * 8 + 2 * tig];
                    v1 = sm[O_BASE + (2 * kg + 1) * 8 + 2 * tig + 1];
                    Cb[mt][0] = v0; Cb[mt][1] = v1; Cb[mt][2] = v0; Cb[mt][3] = v1;
                }
                #pragma unroll
                for (int k = 0; k < 2; k++) {
                    u32 ba0 = WT[((2 * kg) * 8 + grp) * SW0G + k * 8 + tig];
                    u32 ba1 = WT[((2 * kg) * 8 + grp) * SW0G + k * 8 + 4 + tig];
                    u32 bb0 = WT[((2 * kg + 1) * 8 + grp) * SW0G + k * 8 + tig];
                    u32 bb1 = WT[((2 * kg + 1) * 8 + grp) * SW0G + k * 8 + 4 + tig];
                    #pragma unroll
                    for (int mt = 0; mt < 2; mt++) {
                        mma16(Ca[mt], Ag[mt][k], ba0, ba1);
                        mma16(Cb[mt], Ag[mt][k], bb0, bb1);
                    }
                }
                #pragma unroll
                for (int mt = 0; mt < 2; mt++) {
                    A1[mt][kg][0] = pkrelu(Ca[mt][0], Ca[mt][1]);
                    A1[mt][kg][1] = pkrelu(Ca[mt][2], Ca[mt][3]);
                    A1[mt][kg][2] = pkrelu(Cb[mt][0], Cb[mt][1]);
                    A1[mt][kg][3] = pkrelu(Cb[mt][2], Cb[mt][3]);
                }
            }
        }

        // ============ layer 1 -> A2 ============
        u32 A2[2][4][4];
        {
            const u32* WT = smu + O_W1T;
            #pragma unroll
            for (int kg = 0; kg < 4; kg++) {
                float Ca[2][4], Cb[2][4];
                #pragma unroll
                for (int mt = 0; mt < 2; mt++) {
                    float v0 = sm[O_B1 + (2 * kg) * 8 + 2 * tig];
                    float v1 = sm[O_B1 + (2 * kg) * 8 + 2 * tig + 1];
                    Ca[mt][0] = v0; Ca[mt][1] = v1; Ca[mt][2] = v0; Ca[mt][3] = v1;
                    v0 = sm[O_B1 + (2 * kg + 1) * 8 + 2 * tig];
                    v1 = sm[O_B1 + (2 * kg + 1) * 8 + 2 * tig + 1];
                    Cb[mt][0] = v0; Cb[mt][1] = v1; Cb[mt][2] = v0; Cb[mt][3] = v1;
                }
                #pragma unroll
                for (int k = 0; k < 4; k++) {
                    u32 ba0 = WT[((2 * kg) * 8 + grp) * SW1 + k * 8 + tig];
                    u32 ba1 = WT[((2 * kg) * 8 + grp) * SW1 + k * 8 + 4 + tig];
                    u32 bb0 = WT[((2 * kg + 1) * 8 + grp) * SW1 + k * 8 + tig];
                    u32 bb1 = WT[((2 * kg + 1) * 8 + grp) * SW1 + k * 8 + 4 + tig];
                    #pragma unroll
                    for (int mt = 0; mt < 2; mt++) {
                        mma16(Ca[mt], A1[mt][k], ba0, ba1);
                        mma16(Cb[mt], A1[mt][k], bb0, bb1);
                    }
                }
                #pragma unroll
                for (int mt = 0; mt < 2; mt++) {
                    A2[mt][kg][0] = pkrelu(Ca[mt][0], Ca[mt][1]);
                    A2[mt][kg][1] = pkrelu(Ca[mt][2], Ca[mt][3]);
                    A2[mt][kg][2] = pkrelu(Cb[mt][0], Cb[mt][1]);
                    A2[mt][kg][3] = pkrelu(Cb[mt][2], Cb[mt][3]);
                }
            }
        }

        // ============ layer 2 -> logits ============
        {
            const u32* WT = smu + O_W2T;
            float bv0 = sm[O_B2 + 2 * tig];
            float bv1 = sm[O_B2 + 2 * tig + 1];
            float C0[4] = {bv0, bv1, bv0, bv1};
            float C1[4] = {bv0, bv1, bv0, bv1};
            #pragma unroll
            for (int k = 0; k < 4; k++) {
                u32 bb0 = WT[grp * SW2 + k * 8 + tig];
                u32 bb1 = WT[grp * SW2 + k * 8 + 4 + tig];
                mma16(C0, A2[0][k], bb0, bb1);
                mma16(C1, A2[1][k], bb0, bb1);
            }
            const int r1 = r0 + 16;
            if (2 * tig < 3) {
                sm[O_COLB + r0 * SCB + 2 * tig]        = C0[0];
                sm[O_COLB + (r0 + 8) * SCB + 2 * tig]  = C0[2];
                sm[O_COLB + r1 * SCB + 2 * tig]        = C1[0];
                sm[O_COLB + (r1 + 8) * SCB + 2 * tig]  = C1[2];
            }
            if (2 * tig + 1 < 3) {
                sm[O_COLB + r0 * SCB + 2 * tig + 1]       = C0[1];
                sm[O_COLB + (r0 + 8) * SCB + 2 * tig + 1] = C0[3];
                sm[O_COLB + r1 * SCB + 2 * tig + 1]       = C1[1];
                sm[O_COLB + (r1 + 8) * SCB + 2 * tig + 1] = C1[3];
            }
        }
        __syncwarp();

        // ============ phase 3 ============
        float l0 = sm[O_COLB + tid * SCB + 0];
        float l1 = sm[O_COLB + tid * SCB + 1];
        float l2 = sm[O_COLB + tid * SCB + 2];
        float c0 = 1.0f / (1.0f + expf(-l0));
        float c1 = 1.0f / (1.0f + expf(-l1));
        float c2 = 1.0f / (1.0f + expf(-l2));
        float rr = cw * c0, gg = cw * c1, bb = cw * c2;
        #pragma unroll
        for (int o = 16; o; o >>= 1) {
            rr += __shfl_xor_sync(0xffffffffu, rr, o);
            gg += __shfl_xor_sync(0xffffffffu, gg, o);
            bb += __shfl_xor_sync(0xffffffffu, bb, o);
        }
        if (lane == 0) {
            sm[O_COL + warp * 3 + 0] = rr;
            sm[O_COL + warp * 3 + 1] = gg;
            sm[O_COL + warp * 3 + 2] = bb;
        }
        __syncthreads();   // (C)
        if (tid < 3) {
            outColor[(size_t)row * 3 + tid] =
                sm[O_COL + tid] + sm[O_COL + 3 + tid] +
                sm[O_COL + 6 + tid] + sm[O_COL + 9 + tid];
        }
        row = nrow;
    }
}

extern "C" void kernel_launch(void* const* d_in, const int* in_sizes, int n_in,
                              void* d_out, int out_size)
{
    const int*    x  = (const int*)d_in[0];
    const float*  dv = (const float*)d_in[1];
    const float4* gw = (const float4*)d_in[2];
    const float*  W0 = (const float*)d_in[3];
    const float*  b0 = (const float*)d_in[4];
    const float*  W1 = (const float*)d_in[5];
    const float*  b1 = (const float*)d_in[6];
    const float*  W2 = (const float*)d_in[7];
    const float*  b2 = (const float*)d_in[8];

    const int B = in_sizes[0] / (BN * LVL);   // 16384
    float* outSigma = (float*)d_out;
    float* outColor = (float*)d_out + (size_t)B * BN;

    cudaFuncSetAttribute(surf_v12,
                         cudaFuncAttributeMaxDynamicSharedMemorySize, SMEM_BYTES);

    int grid = B < 444 ? B : 444;   // 3 blocks/SM persistent
    surf_v12<<<grid, 128, SMEM_BYTES>>>(x, dv, gw, W0, b0, W1, b1, W2, b2,
                                        outSigma, outColor, B);
}